// round 15
// baseline (speedup 1.0000x reference)
#include <cuda_runtime.h>
#include <cuda.h>
#include <cuda_fp16.h>
#include <cstdint>

// out[M,1024] = merged[M,4096] @ W[4096,1024], fp32 via single-pass fp16 HMMA.
// R14: R13 persistent TMA pipeline + wait-ahead: each warp validates chunk c+1
// BEFORE the per-chunk sync, while its own chunk-c MMAs drain the tensor pipe.
// Removes the ~90-cyc TRYWAIT from the per-chunk critical path (125->~50 cyc).

#define PATCH 14
#define HID   1024
#define KTOT  4096
#define MPAD  15104

#define BM 64
#define BN 128
#define BK 64
#define NCHUNK (KTOT / BK)          // 64
#define TILE_A  8192                // 64 rows x 128 B (SW128)
#define TILE_BB 16384               // 128 rows x 128 B
#define STAGE_B (TILE_A + TILE_BB)  // 24576
#define NSTAGE 3
#define SMEM_DATA 1024
#define SMEM_TOTAL (SMEM_DATA + NSTAGE * STAGE_B)   // 74752 -> 3 CTAs/SM

#define NCTAS 444                   // 148 SMs x 3

#define OFF_FULL(s) ((s) * 8)
#define OFF_TILE 64                 // smem slot for broadcast tile index

// scratch (static device memory — no runtime allocation)
__device__ __align__(128) __half g_Ah[(size_t)MPAD * KTOT];
__device__ __align__(128) __half g_Bh[(size_t)HID * KTOT];
__device__ int g_tile_ctr;

// ─── PTX helpers ────────────────────────────────────────────────────────────
__device__ __forceinline__ uint32_t smem_u32(const void* p) {
    uint32_t a;
    asm("{ .reg .u64 t; cvta.to.shared.u64 t, %1; cvt.u32.u64 %0, t; }" : "=r"(a) : "l"(p));
    return a;
}
#define MBAR_INIT(addr, cnt) \
    asm volatile("mbarrier.init.shared.b64 [%0], %1;" :: "r"(addr), "r"(cnt) : "memory")
#define MBAR_EXPECT_TX(addr, bytes) \
    asm volatile("mbarrier.arrive.expect_tx.shared.b64 _, [%0], %1;" :: "r"(addr), "r"(bytes) : "memory")
#define MBAR_WAIT(addr, parity) do {                                          \
    uint32_t _m = (addr), _p = (parity), _d;                                  \
    asm volatile("{\n\t.reg .pred p;\n\t"                                     \
        "mbarrier.try_wait.parity.acquire.cta.shared::cta.b64 p, [%1], %2;\n\t" \
        "selp.b32 %0, 1, 0, p;\n\t}"                                          \
        : "=r"(_d) : "r"(_m), "r"(_p) : "memory");                            \
    if (!_d) {                                                                \
        asm volatile("{\n\t.reg .pred P1;\n\t"                                \
            "WL_%=:\n\t"                                                      \
            "mbarrier.try_wait.parity.acquire.cta.shared::cta.b64 P1, [%0], %1, 0x989680;\n\t" \
            "@P1 bra.uni WD_%=;\n\t"                                          \
            "bra.uni WL_%=;\n\t"                                              \
            "WD_%=:\n\t}" :: "r"(_m), "r"(_p) : "memory");                    \
    }                                                                         \
} while (0)

__device__ __forceinline__ void tma_load_2d(uint32_t smem, const void* map,
                                            int cx, int cy, uint32_t mbar) {
    asm volatile(
        "cp.async.bulk.tensor.2d.shared::cta.global.tile.mbarrier::complete_tx::bytes "
        "[%0], [%1, {%2, %3}], [%4];"
        :: "r"(smem), "l"(map), "r"(cx), "r"(cy), "r"(mbar) : "memory");
}
__device__ __forceinline__ void ldsm_x4(uint32_t* r, uint32_t addr) {
    asm volatile("ldmatrix.sync.aligned.m8n8.x4.shared.b16 {%0,%1,%2,%3}, [%4];"
        : "=r"(r[0]), "=r"(r[1]), "=r"(r[2]), "=r"(r[3]) : "r"(addr));
}
__device__ __forceinline__ void mma_f16(float* c, const uint32_t* a, const uint32_t* b) {
    asm volatile("mma.sync.aligned.m16n8k16.row.col.f32.f16.f16.f32 "
        "{%0,%1,%2,%3}, {%4,%5,%6,%7}, {%8,%9}, {%0,%1,%2,%3};"
        : "+f"(c[0]), "+f"(c[1]), "+f"(c[2]), "+f"(c[3])
        : "r"(a[0]), "r"(a[1]), "r"(a[2]), "r"(a[3]), "r"(b[0]), "r"(b[1]));
}

// ─── prep: A gather/convert + pad zeroing + W transpose + counter reset ─────
__global__ void convert_AW_kernel(const float* __restrict__ feat,
                                  const float* __restrict__ Wm,
                                  const int* __restrict__ sizes,
                                  int n_images, int M, int n_pad) {
    __shared__ int   s_src[4];
    __shared__ float tile[32][33];
    const int bx  = blockIdx.x;
    const int tid = threadIdx.x;
    if (bx == 0 && tid == 0) g_tile_ctr = 0;   // reset work-steal counter
    if (bx < M) {
        if (tid < 4) {
            int toff = 0, moff = 0, src = 0;
            for (int i = 0; i < n_images; i++) {
                const int h = sizes[2 * i] / PATCH, w = sizes[2 * i + 1] / PATCH;
                const int w2 = w >> 1, mr = (h >> 1) * w2;
                if (bx < moff + mr) {
                    const int r = bx - moff;
                    const int gr = r / w2, gc = r - gr * w2;
                    src = toff + (2 * gr + (tid >> 1)) * w + 2 * gc + (tid & 1);
                    break;
                }
                toff += h * w; moff += mr;
            }
            s_src[tid] = src;
        }
        __syncthreads();
        const int ki = tid >> 6;
        const int c  = (tid & 63) * 16;
        const float4* src = (const float4*)(feat + (size_t)s_src[ki] * HID + c);
        const float4 x0 = src[0], x1 = src[1], x2 = src[2], x3 = src[3];
        __half2 h[8];
        h[0] = __floats2half2_rn(x0.x, x0.y); h[1] = __floats2half2_rn(x0.z, x0.w);
        h[2] = __floats2half2_rn(x1.x, x1.y); h[3] = __floats2half2_rn(x1.z, x1.w);
        h[4] = __floats2half2_rn(x2.x, x2.y); h[5] = __floats2half2_rn(x2.z, x2.w);
        h[6] = __floats2half2_rn(x3.x, x3.y); h[7] = __floats2half2_rn(x3.z, x3.w);
        float4* dst = (float4*)(g_Ah + (size_t)bx * KTOT + ki * HID + c);
        dst[0] = *(float4*)&h[0];
        dst[1] = *(float4*)&h[4];
    } else if (bx < M + n_pad) {
        float4* dst = (float4*)(g_Ah + (size_t)bx * KTOT) + tid * 2;
        dst[0] = make_float4(0.f, 0.f, 0.f, 0.f);
        dst[1] = make_float4(0.f, 0.f, 0.f, 0.f);
    } else {
        const int b  = bx - M - n_pad;
        const int k0 = (b & 127) * 32, n0 = (b >> 7) * 32;
        const int tx = tid & 31, ty = tid >> 5;
        #pragma unroll
        for (int i = 0; i < 4; i++)
            tile[ty + i * 8][tx] = Wm[(size_t)(k0 + ty + i * 8) * HID + n0 + tx];
        __syncthreads();
        #pragma unroll
        for (int i = 0; i < 4; i++) {
            const float x = tile[tx][ty + i * 8];
            g_Bh[(size_t)(n0 + ty + i * 8) * KTOT + k0 + tx] = __float2half_rn(x);
        }
    }
}

// ─── main GEMM: persistent, work-stealing, TMA ring, wait-ahead ─────────────
__global__ __launch_bounds__(128, 3) void gemm_tma_kernel(
    const __grid_constant__ CUtensorMap tmA,
    const __grid_constant__ CUtensorMap tmB,
    float* __restrict__ out, int M, int ntiles)
{
    extern __shared__ __align__(1024) char smem[];
    const uint32_t sb = smem_u32(smem);
    const int tid  = threadIdx.x;
    const int lane = tid & 31;
    const int wid  = tid >> 5;
    const int wm   = wid & 1;
    const int wn   = wid >> 1;

    if (tid == 0) {
        #pragma unroll
        for (int s = 0; s < NSTAGE; s++)
            MBAR_INIT(sb + OFF_FULL(s), 1);
    }
    __syncthreads();

    const int arow = wm * 32 + (lane & 15);
    const int asel = lane >> 4;
    const int aswz = arow & 7;
    const int brow = wn * 64 + ((lane >> 4) & 1) * 8 + (lane & 7);
    const int bsel = (lane >> 3) & 1;
    const int bswz = brow & 7;
    const int g = lane >> 2, t4 = lane & 3;

    int cst = 0, cph = 0;   // ring cursor, rolls across tiles (linear parity)

    while (true) {
        if (tid == 0)
            *(volatile int*)(smem + OFF_TILE) = atomicAdd(&g_tile_ctr, 1);
        __syncthreads();
        const int t = *(volatile int*)(smem + OFF_TILE);
        __syncthreads();
        if (t >= ntiles) break;
        const int m0 = (t >> 3) * BM;
        const int n0 = (t & 7) * BN;

        // prologue: chunks 0,1 into ring slots cst, cst+1 (both consumed by
        // the time the previous tile's loop + syncs finished)
        if (tid == 0) {
            int ps = cst;
            #pragma unroll
            for (int pc = 0; pc < 2; pc++) {
                const uint32_t st = sb + SMEM_DATA + ps * STAGE_B;
                MBAR_EXPECT_TX(sb + OFF_FULL(ps), STAGE_B);
                tma_load_2d(st,          &tmA, pc * BK, m0, sb + OFF_FULL(ps));
                tma_load_2d(st + TILE_A, &tmB, pc * BK, n0, sb + OFF_FULL(ps));
                if (++ps == NSTAGE) ps = 0;
            }
        }

        float acc[2][8][4];
        #pragma unroll
        for (int i = 0; i < 2; i++)
            #pragma unroll
            for (int j = 0; j < 8; j++)
                #pragma unroll
                for (int q = 0; q < 4; q++) acc[i][j][q] = 0.0f;

        int pslot = (cst + 2) % NSTAGE;     // slot for chunk c+2

        // validate chunk 0 before the loop
        MBAR_WAIT(sb + OFF_FULL(cst), cph);

        #pragma unroll 1
        for (int c = 0; c < NCHUNK; c++) {
            // compute chunk c (stage cst, already validated)
            {
                const uint32_t base = sb + SMEM_DATA + cst * STAGE_B;
                #pragma unroll
                for (int kk = 0; kk < 4; kk++) {
                    uint32_t a[2][4], b[4][4];
                    const uint32_t acol = (uint32_t)(((kk * 2 + asel) ^ aswz) << 4);
                    const uint32_t bcol = (uint32_t)(((kk * 2 + bsel) ^ bswz) << 4);
                    #pragma unroll
                    for (int i = 0; i < 2; i++)
                        ldsm_x4(a[i], base + (arow + i * 16) * 128 + acol);
                    #pragma unroll
                    for (int jj = 0; jj < 4; jj++)
                        ldsm_x4(b[jj], base + TILE_A + (brow + jj * 16) * 128 + bcol);
                    #pragma unroll
                    for (int i = 0; i < 2; i++)
                        #pragma unroll
                        for (int j = 0; j < 8; j++)
                            mma_f16(acc[i][j], a[i], &b[j >> 1][(j & 1) * 2]);
                }
            }

            // wait-ahead: validate chunk c+1 while this warp's chunk-c MMAs
            // drain the tensor pipe (~512 cyc of shadow vs ~90 cyc wait)
            if (c + 1 < NCHUNK) {
                const int ns  = (cst + 1 == NSTAGE) ? 0 : cst + 1;
                const int np  = (cst == NSTAGE - 1) ? (cph ^ 1) : cph;
                MBAR_WAIT(sb + OFF_FULL(ns), np);
            }

            // recycle: all warps past compute(c) => stage pslot ((c-1)%3) free
            __syncthreads();
            if (tid == 0 && c + 2 < NCHUNK) {
                const int pc = c + 2;
                const uint32_t st = sb + SMEM_DATA + pslot * STAGE_B;
                MBAR_EXPECT_TX(sb + OFF_FULL(pslot), STAGE_B);
                tma_load_2d(st,          &tmA, pc * BK, m0, sb + OFF_FULL(pslot));
                tma_load_2d(st + TILE_A, &tmB, pc * BK, n0, sb + OFF_FULL(pslot));
            }
            if (++pslot == NSTAGE) pslot = 0;
            if (++cst == NSTAGE) { cst = 0; cph ^= 1; }
        }

        // epilogue for this tile
        #pragma unroll
        for (int i = 0; i < 2; i++) {
            #pragma unroll
            for (int j = 0; j < 8; j++) {
                const int r  = m0 + wm * 32 + i * 16 + g;
                const int cc = n0 + wn * 64 + j * 8 + t4 * 2;
                if (r < M)
                    *(float2*)(out + (size_t)r * HID + cc) =
                        make_float2(acc[i][j][0], acc[i][j][1]);
                if (r + 8 < M)
                    *(float2*)(out + (size_t)(r + 8) * HID + cc) =
                        make_float2(acc[i][j][2], acc[i][j][3]);
            }
        }
    }
}

// ─── host ───────────────────────────────────────────────────────────────────
typedef CUresult (*PFN_encodeTiled)(
    CUtensorMap*, CUtensorMapDataType, cuuint32_t, void*,
    const cuuint64_t*, const cuuint64_t*, const cuuint32_t*, const cuuint32_t*,
    CUtensorMapInterleave, CUtensorMapSwizzle, CUtensorMapL2promotion,
    CUtensorMapFloatOOBfill);

static void make_map(PFN_encodeTiled fn, CUtensorMap* tm, void* ptr,
                     uint64_t d0, uint64_t d1, uint32_t b0, uint32_t b1) {
    cuuint64_t dims[2] = {d0, d1};
    cuuint64_t strides[1] = {d0 * sizeof(__half)};
    cuuint32_t box[2] = {b0, b1};
    cuuint32_t es[2] = {1, 1};
    fn(tm, CU_TENSOR_MAP_DATA_TYPE_FLOAT16, 2, ptr, dims, strides, box, es,
       CU_TENSOR_MAP_INTERLEAVE_NONE, CU_TENSOR_MAP_SWIZZLE_128B,
       CU_TENSOR_MAP_L2_PROMOTION_L2_128B, CU_TENSOR_MAP_FLOAT_OOB_FILL_NONE);
}

extern "C" void kernel_launch(void* const* d_in, const int* in_sizes, int n_in,
                              void* d_out, int out_size) {
    const float* feat  = (const float*)d_in[0];
    const int*   sizes = (const int*)  d_in[1];
    const float* Wm    = (const float*)d_in[2];
    float* out = (float*)d_out;

    const int n_images = in_sizes[1] / 2;
    const int M        = out_size / HID;
    const int n_pad    = MPAD - M;
    const int ntiles   = ((M + BM - 1) / BM) * (HID / BN);   // 234 * 8 = 1872

    convert_AW_kernel<<<M + n_pad + (KTOT / 32) * (HID / 32), 256>>>(
        feat, Wm, sizes, n_images, M, n_pad);

    static bool init_done = false;
    static CUtensorMap tmA, tmB;
    if (!init_done) {
        PFN_encodeTiled encode = nullptr;
        cudaDriverEntryPointQueryResult qr;
        cudaGetDriverEntryPointByVersion("cuTensorMapEncodeTiled", (void**)&encode,
                                         12000, cudaEnableDefault, &qr);
        void *pA, *pB;
        cudaGetSymbolAddress(&pA, g_Ah);
        cudaGetSymbolAddress(&pB, g_Bh);
        make_map(encode, &tmA, pA, KTOT, MPAD, BK, BM);
        make_map(encode, &tmB, pB, KTOT, HID,  BK, BN);
        cudaFuncSetAttribute(gemm_tma_kernel,
                             cudaFuncAttributeMaxDynamicSharedMemorySize, SMEM_TOTAL);
        init_done = true;
    }
    gemm_tma_kernel<<<NCTAS, 128, SMEM_TOTAL>>>(tmA, tmB, out, M, ntiles);
}